// round 14
// baseline (speedup 1.0000x reference)
#include <cuda_runtime.h>
#include <cuda_fp16.h>
#include <cstdint>
#include <cstddef>

#define H_   160
#define W_   160
#define B_   4
#define HW   (H_ * W_)
#define PIX  (B_ * HW)          // 102400
#define K2   2304               // 9 * 256
#define NCHK 36                 // K chunks of 64 (tap-major: tap*4 + cq)

// ---------------- scratch (device globals; no allocation allowed) ----------
__device__ float  g_buf1[3][(size_t)B_ * 256 * HW];
__device__ float  g_buf2[3][(size_t)B_ * 128 * HW];
__device__ __half g_wt1[3][2 * 36 * 8192];        // packed fp16 conv1 weights
__device__ __half g_wt2[3][1 * 36 * 8192];        // packed fp16 conv2 weights
__device__ float  g_sc1[3][256], g_bi1[3][256];
__device__ float  g_sc2[3][128], g_bi2[3][128];
__device__ float  g_wcat[2 * 128 * 9];
__device__ float  g_bcat[2];

__device__ __forceinline__ uint32_t smem_u32(const void* p) {
    uint32_t a;
    asm("{ .reg .u64 t; cvta.to.shared.u64 t, %1; cvt.u32.u64 %0, t; }" : "=r"(a) : "l"(p));
    return a;
}
__device__ __forceinline__ void cp_async16(uint32_t saddr, const void* g) {
    asm volatile("cp.async.cg.shared.global [%0], [%1], 16;" :: "r"(saddr), "l"(g));
}
#define CP_COMMIT() asm volatile("cp.async.commit_group;" ::: "memory")
#define CP_WAIT0()  asm volatile("cp.async.wait_group 0;" ::: "memory")

__device__ __forceinline__ uint32_t pack2h(float x, float y) {
    __half2 h = __floats2half2_rn(x, y);
    return *(uint32_t*)&h;
}

// mma.sync m16n8k16 fp16 with fp32 accum (baseline PTX sm_80+)
__device__ __forceinline__ void mma16(float* d, const uint32_t* a, uint32_t b0, uint32_t b1) {
    asm volatile(
        "mma.sync.aligned.m16n8k16.row.col.f32.f16.f16.f32 "
        "{%0,%1,%2,%3}, {%4,%5,%6,%7}, {%8,%9}, {%0,%1,%2,%3};"
        : "+f"(d[0]), "+f"(d[1]), "+f"(d[2]), "+f"(d[3])
        : "r"(a[0]), "r"(a[1]), "r"(a[2]), "r"(a[3]), "r"(b0), "r"(b1));
}

// smem per stage: A fragment-packed 16384 B + B 16 rows x 66 uint2 (8448 B)
#define BROW_U2   66
#define A_BYTES   16384
#define B_BYTES   (16 * BROW_U2 * 8)     // 8448
#define STG_BYTES (A_BYTES + B_BYTES)    // 24832
#define SMEM_DYN  (2 * STG_BYTES)        // 49664

// ---------------- weight pack: [oc][ci][tap] -> m16n8k16 fragment order ----
__global__ void wt_pack(const float* __restrict__ w, __half* __restrict__ dst, int Cout)
{
    int i = blockIdx.x * 256 + threadIdx.x;
    if (i >= Cout * K2) return;
    int h     = i & 1;
    int jreg  = (i >> 1) & 3;
    int lane  = (i >> 3) & 31;
    int ocq   = (i >> 8) & 7;
    int ks    = (i >> 11) & 3;
    int chunk = (i >> 13) % NCHK;
    int ocblk = i / (NCHK * 8192);
    int q = lane & 3, r = lane >> 2;
    int row16 = r + 8 * (jreg & 1);
    int kk    = 2 * q + h + 8 * (jreg >> 1);
    int oc  = ocblk * 128 + ocq * 16 + row16;
    int ci  = (chunk & 3) * 64 + ks * 16 + kk;
    int tap = chunk >> 2;
    dst[i] = __float2half_rn(w[((size_t)oc * 256 + ci) * 9 + tap]);
}

// ---------------- concat two 1-channel head weights -------------------------
__global__ void concat_heads(const float* __restrict__ wa, const float* __restrict__ wb,
                             const float* __restrict__ ba, const float* __restrict__ bb,
                             float* __restrict__ w, float* __restrict__ bias)
{
    int i = blockIdx.x * 256 + threadIdx.x;
    if (i < 1152) w[i] = wa[i];
    else if (i < 2304) w[i] = wb[i - 1152];
    if (i == 0) { bias[0] = ba[0]; bias[1] = bb[0]; }
}

// ---------------- fp16 mma.sync implicit-GEMM 3x3 conv ----------------------
// grid: (PIX/64, Cout/128)  block: 128 threads (4 warps, warp = 64oc x 32px)
// 3 CTAs/SM (12 warps) for HMMA latency hiding.
template <bool HAS_BN>
__global__ __launch_bounds__(128, 3)
void conv3x3_mma(const float* __restrict__ X, const __half* __restrict__ wtp,
                 float* __restrict__ Y, int Cout,
                 const float* __restrict__ bnsc, const float* __restrict__ bnbi)
{
    extern __shared__ char sm[];
    const uint32_t smb = smem_u32(sm);

    const int tid  = threadIdx.x;
    const int wid  = tid >> 5;          // 0..3
    const int lane = tid & 31;
    const int r    = lane >> 2;
    const int q    = lane & 3;

    const int p0   = blockIdx.x * 64;
    const int oc0  = blockIdx.y * 128;
    const int bimg = p0 / HW;
    const int hw0  = p0 - bimg * HW;
    const float*  Xb  = X + (size_t)bimg * 256 * HW;
    const __half* wcb = wtp + (size_t)blockIdx.y * (NCHK * 8192);

    const int ocb = (wid & 1) * 64;     // warp oc sub-block (4 x m16)
    const int pxb = (wid >> 1) * 32;    // warp px sub-block (4 x n8)
    const int cw  = 2 * wid;            // B staging channel base within k16

    int pg[2], hh[2], ww[2];
    #pragma unroll
    for (int g = 0; g < 2; g++) {
        int p = hw0 + g * 32 + lane;
        pg[g] = p; hh[g] = p / W_; ww[g] = p % W_;
    }

    float acc[4][4][4];
    #pragma unroll
    for (int mt = 0; mt < 4; mt++)
        #pragma unroll
        for (int nt = 0; nt < 4; nt++)
            #pragma unroll
            for (int i = 0; i < 4; i++) acc[mt][nt][i] = 0.f;

    uint2 rb[4][2];    // [ks][px group]

    auto copyA = [&](int c, int s) {
        const char* g = (const char*)wcb + (size_t)c * A_BYTES + tid * 16;
        uint32_t d = smb + s * STG_BYTES + tid * 16;
        #pragma unroll
        for (int i = 0; i < 8; i++)
            cp_async16(d + i * 2048, g + i * 2048);
    };

    auto stageB = [&](int c) {
        const int tap = c >> 2;
        const int ci0 = (c & 3) << 6;
        const int dh  = tap / 3 - 1;
        const int dw  = tap % 3 - 1;
        #pragma unroll
        for (int ks = 0; ks < 4; ks++) {
            const int ch = ci0 + 16 * ks + cw;
            float sc0, sc1, sc2, sc3, bi0, bi1, bi2, bi3;
            if (HAS_BN) {
                sc0 = bnsc[ch];     bi0 = bnbi[ch];
                sc1 = bnsc[ch + 1]; bi1 = bnbi[ch + 1];
                sc2 = bnsc[ch + 8]; bi2 = bnbi[ch + 8];
                sc3 = bnsc[ch + 9]; bi3 = bnbi[ch + 9];
            }
            const float* base = Xb + (size_t)ch * HW + dh * W_ + dw;
            #pragma unroll
            for (int g = 0; g < 2; g++) {
                bool v = (unsigned)(hh[g] + dh) < (unsigned)H_ &&
                         (unsigned)(ww[g] + dw) < (unsigned)W_;
                const float* sp = base + pg[g];
                float x0 = v ? sp[0]              : 0.f;
                float x1 = v ? sp[(size_t)HW]     : 0.f;
                float x2 = v ? sp[(size_t)8 * HW] : 0.f;
                float x3 = v ? sp[(size_t)9 * HW] : 0.f;
                if (HAS_BN) {
                    x0 = v ? fmaxf(fmaf(x0, sc0, bi0), 0.f) : 0.f;
                    x1 = v ? fmaxf(fmaf(x1, sc1, bi1), 0.f) : 0.f;
                    x2 = v ? fmaxf(fmaf(x2, sc2, bi2), 0.f) : 0.f;
                    x3 = v ? fmaxf(fmaf(x3, sc3, bi3), 0.f) : 0.f;
                }
                rb[ks][g] = make_uint2(pack2h(x0, x1), pack2h(x2, x3));
            }
        }
    };

    auto stsB = [&](int s) {
        uint2* sB2 = (uint2*)(sm + s * STG_BYTES + A_BYTES);
        #pragma unroll
        for (int ks = 0; ks < 4; ks++)
            #pragma unroll
            for (int g = 0; g < 2; g++)
                sB2[(ks * 4 + wid) * BROW_U2 + g * 32 + lane] = rb[ks][g];
    };

    auto compute = [&](int s) {
        const char*  sbase = sm + s * STG_BYTES;
        const uint2* sB2   = (const uint2*)(sbase + A_BYTES);
        #pragma unroll
        for (int ks = 0; ks < 4; ks++) {
            const uint4* aP = (const uint4*)sbase + (ks * 8 + (wid & 1) * 4) * 32 + lane;
            uint32_t a[4][4];
            #pragma unroll
            for (int mt = 0; mt < 4; mt++) {
                uint4 A = aP[mt * 32];
                a[mt][0] = A.x; a[mt][1] = A.y; a[mt][2] = A.z; a[mt][3] = A.w;
            }
            const uint2* bP = sB2 + (ks * 4 + q) * BROW_U2 + pxb + r;
            #pragma unroll
            for (int nt = 0; nt < 4; nt++) {
                uint2 b = bP[nt * 8];
                #pragma unroll
                for (int mt = 0; mt < 4; mt++)
                    mma16(acc[mt][nt], a[mt], b.x, b.y);
            }
        }
    };

    // prologue
    copyA(0, 0); CP_COMMIT();
    stageB(0); stsB(0);
    CP_WAIT0();
    __syncthreads();

    for (int c = 0; c < NCHK; c++) {
        const int cur = c & 1, nxt = cur ^ 1;
        if (c + 1 < NCHK) {
            copyA(c + 1, nxt); CP_COMMIT();
            stageB(c + 1);
        }
        compute(cur);
        if (c + 1 < NCHK) {
            stsB(nxt);
            CP_WAIT0();
            __syncthreads();
        }
    }

    #pragma unroll
    for (int mt = 0; mt < 4; mt++) {
        const int oc = oc0 + ocb + mt * 16 + r;
        float* Yr = Y + ((size_t)bimg * Cout + oc) * HW + hw0 + pxb + q * 2;
        #pragma unroll
        for (int nt = 0; nt < 4; nt++) {
            *(float2*)(Yr + nt * 8)                  = make_float2(acc[mt][nt][0], acc[mt][nt][1]);
            *(float2*)(Yr + nt * 8 + 8 * (size_t)HW) = make_float2(acc[mt][nt][2], acc[mt][nt][3]);
        }
    }
}

// ---------------- per-channel batch stats -> fused scale/bias ---------------
__global__ __launch_bounds__(1024)
void bn_stats(const float* __restrict__ X, int C,
              const float* __restrict__ gamma, const float* __restrict__ beta,
              float* __restrict__ osc, float* __restrict__ obi)
{
    const int c = blockIdx.x;
    float s = 0.f, s2 = 0.f;
    for (int b = 0; b < B_; b++) {
        const float* qp = X + ((size_t)b * C + c) * HW;
        for (int i = threadIdx.x; i < HW; i += 1024) {
            float v = qp[i];
            s += v; s2 += v * v;
        }
    }
    __shared__ float rs[1024], rs2[1024];
    rs[threadIdx.x] = s; rs2[threadIdx.x] = s2;
    __syncthreads();
    for (int o = 512; o > 0; o >>= 1) {
        if (threadIdx.x < o) {
            rs[threadIdx.x]  += rs[threadIdx.x + o];
            rs2[threadIdx.x] += rs2[threadIdx.x + o];
        }
        __syncthreads();
    }
    if (threadIdx.x == 0) {
        const float cnt = (float)(B_ * HW);
        float m   = rs[0] / cnt;
        float var = rs2[0] / cnt - m * m;
        float is  = rsqrtf(var + 1e-5f);
        float scl = gamma[c] * is;
        osc[c] = scl;
        obi[c] = beta[c] - m * scl;
    }
}

// ---------------- head conv: 3x3 + bias, BN+ReLU fused on input -------------
#define HTH 16
#define HTW 32

template <int CO>
__global__ __launch_bounds__(256)
void head_conv(const float* __restrict__ X, const float* __restrict__ Wt,
               const float* __restrict__ bias, float* __restrict__ Y, int Cin,
               const float* __restrict__ bnsc, const float* __restrict__ bnbi,
               size_t strideC, size_t strideB)
{
    const int tile = blockIdx.x;
    const int tw0  = (tile % (W_ / HTW)) * HTW;
    const int th0  = (tile / (W_ / HTW)) * HTH;
    const int b    = blockIdx.z;
    const int t    = threadIdx.x;
    const int col  = t & 31;
    const int rp   = (t >> 5) * 2;

    __shared__ float sX[8][HTH + 2][HTW + 4];
    __shared__ float sW[8][9][CO];

    float acc[2][CO];
    #pragma unroll
    for (int r = 0; r < 2; r++)
        #pragma unroll
        for (int o = 0; o < CO; o++) acc[r][o] = 0.f;

    const float* Xb = X + (size_t)b * Cin * HW;

    for (int ci0 = 0; ci0 < Cin; ci0 += 8) {
        __syncthreads();
        for (int e = t; e < 8 * (HTH + 2) * 34; e += 256) {
            int ci  = e / ((HTH + 2) * 34);
            int rem = e % ((HTH + 2) * 34);
            int r   = rem / 34;
            int c   = rem % 34;
            int gh  = th0 + r - 1;
            int gw  = tw0 + c - 1;
            float v = 0.f;
            if (gh >= 0 && gh < H_ && gw >= 0 && gw < W_) {
                float x = Xb[(size_t)(ci0 + ci) * HW + gh * W_ + gw];
                v = fmaxf(fmaf(x, bnsc[ci0 + ci], bnbi[ci0 + ci]), 0.f);
            }
            sX[ci][r][c] = v;
        }
        for (int e = t; e < 8 * 9 * CO; e += 256) {
            int ci  = e / (9 * CO);
            int rem = e % (9 * CO);
            int tap = rem / CO;
            int oc  = rem % CO;
            sW[ci][tap][oc] = Wt[((size_t)oc * Cin + ci0 + ci) * 9 + tap];
        }
        __syncthreads();

        #pragma unroll 1
        for (int ci = 0; ci < 8; ci++) {
            float xv[4][3];
            #pragma unroll
            for (int rr = 0; rr < 4; rr++)
                #pragma unroll
                for (int cc = 0; cc < 3; cc++)
                    xv[rr][cc] = sX[ci][rp + rr][col + cc];
            #pragma unroll
            for (int oc = 0; oc < CO; oc++) {
                float w[9];
                #pragma unroll
                for (int tp = 0; tp < 9; tp++) w[tp] = sW[ci][tp][oc];
                #pragma unroll
                for (int orow = 0; orow < 2; orow++) {
                    float s = acc[orow][oc];
                    #pragma unroll
                    for (int kh = 0; kh < 3; kh++)
                        #pragma unroll
                        for (int kw = 0; kw < 3; kw++)
                            s += w[kh * 3 + kw] * xv[orow + kh][kw];
                    acc[orow][oc] = s;
                }
            }
        }
    }

    #pragma unroll
    for (int oc = 0; oc < CO; oc++) {
        const float bz = bias[oc];
        #pragma unroll
        for (int orow = 0; orow < 2; orow++) {
            const int h = th0 + rp + orow;
            Y[oc * strideC + b * strideB + h * W_ + tw0 + col] = acc[orow][oc] + bz;
        }
    }
}

// ---------------- launcher ---------------------------------------------------
struct BranchPtrs {
    const float *w1, *g1, *b1, *w2, *g2, *b2;
};

static void run_branch(cudaStream_t st, const float* fpn, const BranchPtrs& P,
                       float* buf1, float* buf2, __half* wt1, __half* wt2,
                       float* sc1, float* bi1, float* sc2, float* bi2)
{
    wt_pack<<<(256 * K2 + 255) / 256, 256, 0, st>>>(P.w1, wt1, 256);
    wt_pack<<<(128 * K2 + 255) / 256, 256, 0, st>>>(P.w2, wt2, 128);
    conv3x3_mma<false><<<dim3(PIX / 64, 2), 128, SMEM_DYN, st>>>(
        fpn, wt1, buf1, 256, nullptr, nullptr);
    bn_stats<<<256, 1024, 0, st>>>(buf1, 256, P.g1, P.b1, sc1, bi1);
    conv3x3_mma<true><<<dim3(PIX / 64, 1), 128, SMEM_DYN, st>>>(
        buf1, wt2, buf2, 128, sc1, bi1);
    bn_stats<<<128, 1024, 0, st>>>(buf2, 128, P.g2, P.b2, sc2, bi2);
}

extern "C" void kernel_launch(void* const* d_in, const int* in_sizes, int n_in,
                              void* d_out, int out_size)
{
    const float* fpn        = (const float*)d_in[0];
    BranchPtrs sc = { (const float*)d_in[1],  (const float*)d_in[2],  (const float*)d_in[3],
                      (const float*)d_in[4],  (const float*)d_in[5],  (const float*)d_in[6] };
    const float* w_shrink   = (const float*)d_in[7];
    const float* bias_shrink= (const float*)d_in[8];
    const float* w_cent     = (const float*)d_in[9];
    const float* bias_cent  = (const float*)d_in[10];
    BranchPtrs pp = { (const float*)d_in[11], (const float*)d_in[12], (const float*)d_in[13],
                      (const float*)d_in[14], (const float*)d_in[15], (const float*)d_in[16] };
    const float* w_p3       = (const float*)d_in[17];
    const float* bias_p3    = (const float*)d_in[18];
    BranchPtrs sh = { (const float*)d_in[19], (const float*)d_in[20], (const float*)d_in[21],
                      (const float*)d_in[22], (const float*)d_in[23], (const float*)d_in[24] };
    const float* w_s3       = (const float*)d_in[25];
    const float* bias_s3    = (const float*)d_in[26];

    float* out = (float*)d_out;

    static cudaStream_t s_st[3];
    static cudaEvent_t  s_fork, s_join[3];
    static int s_init = 0;
    if (!s_init) {
        for (int i = 0; i < 3; i++) {
            cudaStreamCreateWithFlags(&s_st[i], cudaStreamNonBlocking);
            cudaEventCreateWithFlags(&s_join[i], cudaEventDisableTiming);
        }
        cudaEventCreateWithFlags(&s_fork, cudaEventDisableTiming);
        s_init = 1;
    }

    float *buf1[3], *buf2[3];
    __half *wt1[3], *wt2[3];
    float *sc1[3], *bi1[3], *sc2[3], *bi2[3];
    float *wcat, *bcat;
    {
        float *p; __half *hp;
        cudaGetSymbolAddress((void**)&p, g_buf1);
        for (int i = 0; i < 3; i++) buf1[i] = p + (size_t)i * B_ * 256 * HW;
        cudaGetSymbolAddress((void**)&p, g_buf2);
        for (int i = 0; i < 3; i++) buf2[i] = p + (size_t)i * B_ * 128 * HW;
        cudaGetSymbolAddress((void**)&hp, g_wt1);
        for (int i = 0; i < 3; i++) wt1[i] = hp + (size_t)i * 2 * 36 * 8192;
        cudaGetSymbolAddress((void**)&hp, g_wt2);
        for (int i = 0; i < 3; i++) wt2[i] = hp + (size_t)i * 36 * 8192;
        cudaGetSymbolAddress((void**)&p, g_sc1);
        for (int i = 0; i < 3; i++) sc1[i] = p + i * 256;
        cudaGetSymbolAddress((void**)&p, g_bi1);
        for (int i = 0; i < 3; i++) bi1[i] = p + i * 256;
        cudaGetSymbolAddress((void**)&p, g_sc2);
        for (int i = 0; i < 3; i++) sc2[i] = p + i * 128;
        cudaGetSymbolAddress((void**)&p, g_bi2);
        for (int i = 0; i < 3; i++) bi2[i] = p + i * 128;
        cudaGetSymbolAddress((void**)&wcat, g_wcat);
        cudaGetSymbolAddress((void**)&bcat, g_bcat);
    }

    cudaFuncSetAttribute(conv3x3_mma<false>, cudaFuncAttributeMaxDynamicSharedMemorySize, SMEM_DYN);
    cudaFuncSetAttribute(conv3x3_mma<true>,  cudaFuncAttributeMaxDynamicSharedMemorySize, SMEM_DYN);

    dim3 hgrid(50, 1, B_);
    const size_t seg = (size_t)B_ * HW;

    // fork
    cudaEventRecord(s_fork, 0);
    for (int i = 0; i < 3; i++) cudaStreamWaitEvent(s_st[i], s_fork, 0);

    // branch 0: sc -> shrink + centroid (fused CO=2 head via weight concat)
    concat_heads<<<9, 256, 0, s_st[0]>>>(w_shrink, w_cent, bias_shrink, bias_cent,
                                         wcat, bcat);
    run_branch(s_st[0], fpn, sc, buf1[0], buf2[0], wt1[0], wt2[0],
               sc1[0], bi1[0], sc2[0], bi2[0]);
    head_conv<2><<<hgrid, 256, 0, s_st[0]>>>(buf2[0], wcat, bcat, out, 128,
                                             sc2[0], bi2[0], seg, (size_t)HW);

    // branch 1: param (B,2,H,W)
    run_branch(s_st[1], fpn, pp, buf1[1], buf2[1], wt1[1], wt2[1],
               sc1[1], bi1[1], sc2[1], bi2[1]);
    head_conv<2><<<hgrid, 256, 0, s_st[1]>>>(buf2[1], w_p3, bias_p3, out + 2 * seg, 128,
                                             sc2[1], bi2[1], (size_t)HW, (size_t)(2 * HW));

    // branch 2: shift (B,8,H,W)
    run_branch(s_st[2], fpn, sh, buf1[2], buf2[2], wt1[2], wt2[2],
               sc1[2], bi1[2], sc2[2], bi2[2]);
    head_conv<8><<<hgrid, 256, 0, s_st[2]>>>(buf2[2], w_s3, bias_s3, out + 4 * seg, 128,
                                             sc2[2], bi2[2], (size_t)HW, (size_t)(8 * HW));

    // join
    for (int i = 0; i < 3; i++) {
        cudaEventRecord(s_join[i], s_st[i]);
        cudaStreamWaitEvent(0, s_join[i], 0);
    }
}

// round 15
// speedup vs baseline: 1.1695x; 1.1695x over previous
#include <cuda_runtime.h>
#include <cuda_fp16.h>
#include <cstdint>
#include <cstddef>

#define H_   160
#define W_   160
#define B_   4
#define HW   (H_ * W_)
#define PIX  (B_ * HW)          // 102400
#define K2   2304               // 9 * 256
#define NCHK 36                 // K chunks of 64 (tap-major: tap*4 + cq)
#define NBX  (PIX / 128)        // 800

// ---------------- scratch (device globals; no allocation allowed) ----------
__device__ float  g_buf1[3][(size_t)B_ * 256 * HW];
__device__ float  g_buf2[3][(size_t)B_ * 128 * HW];
__device__ __half g_wt1[3][2 * 36 * 8192];        // packed fp16 conv1 weights
__device__ __half g_wt2[3][1 * 36 * 8192];        // packed fp16 conv2 weights
__device__ float  g_sc1[3][256], g_bi1[3][256];
__device__ float  g_sc2[3][128], g_bi2[3][128];
__device__ float  g_wcat[2 * 128 * 9];
__device__ float  g_bcat[2];

__device__ __forceinline__ uint32_t smem_u32(const void* p) {
    uint32_t a;
    asm("{ .reg .u64 t; cvta.to.shared.u64 t, %1; cvt.u32.u64 %0, t; }" : "=r"(a) : "l"(p));
    return a;
}
__device__ __forceinline__ void cp_async16(uint32_t saddr, const void* g) {
    asm volatile("cp.async.cg.shared.global [%0], [%1], 16;" :: "r"(saddr), "l"(g));
}
#define CP_COMMIT() asm volatile("cp.async.commit_group;" ::: "memory")
#define CP_WAIT0()  asm volatile("cp.async.wait_group 0;" ::: "memory")

__device__ __forceinline__ uint32_t pack2h(float x, float y) {
    __half2 h = __floats2half2_rn(x, y);
    return *(uint32_t*)&h;
}

// mma.sync m16n8k16 fp16 with fp32 accum (baseline PTX sm_80+)
__device__ __forceinline__ void mma16(float* d, const uint32_t* a, uint32_t b0, uint32_t b1) {
    asm volatile(
        "mma.sync.aligned.m16n8k16.row.col.f32.f16.f16.f32 "
        "{%0,%1,%2,%3}, {%4,%5,%6,%7}, {%8,%9}, {%0,%1,%2,%3};"
        : "+f"(d[0]), "+f"(d[1]), "+f"(d[2]), "+f"(d[3])
        : "r"(a[0]), "r"(a[1]), "r"(a[2]), "r"(a[3]), "r"(b0), "r"(b1));
}

// smem per stage: A fragment-packed 16384 B + B 16 rows x 132 uint2 (16896 B)
#define BROW_U2   132
#define A_BYTES   16384
#define B_BYTES   (16 * BROW_U2 * 8)     // 16896
#define STG_BYTES (A_BYTES + B_BYTES)    // 33280
#define SMEM_DYN  (2 * STG_BYTES)        // 66560

// ---------------- weight pack: [oc][ci][tap] -> m16n8k16 fragment order ----
__global__ void wt_pack(const float* __restrict__ w, __half* __restrict__ dst, int Cout)
{
    int i = blockIdx.x * 256 + threadIdx.x;
    if (i >= Cout * K2) return;
    int h     = i & 1;
    int jreg  = (i >> 1) & 3;
    int lane  = (i >> 3) & 31;
    int ocq   = (i >> 8) & 7;
    int ks    = (i >> 11) & 3;
    int chunk = (i >> 13) % NCHK;
    int ocblk = i / (NCHK * 8192);
    int q = lane & 3, r = lane >> 2;
    int row16 = r + 8 * (jreg & 1);
    int kk    = 2 * q + h + 8 * (jreg >> 1);
    int oc  = ocblk * 128 + ocq * 16 + row16;
    int ci  = (chunk & 3) * 64 + ks * 16 + kk;
    int tap = chunk >> 2;
    dst[i] = __float2half_rn(w[((size_t)oc * 256 + ci) * 9 + tap]);
}

// ---------------- concat two 1-channel head weights -------------------------
__global__ void concat_heads(const float* __restrict__ wa, const float* __restrict__ wb,
                             const float* __restrict__ ba, const float* __restrict__ bb,
                             float* __restrict__ w, float* __restrict__ bias)
{
    int i = blockIdx.x * 256 + threadIdx.x;
    if (i < 1152) w[i] = wa[i];
    else if (i < 2304) w[i] = wb[i - 1152];
    if (i == 0) { bias[0] = ba[0]; bias[1] = bb[0]; }
}

// ---------------- fp16 mma.sync implicit-GEMM 3x3 conv ----------------------
// grid: (Cout/128, PIX/128)  block: 128 threads (4 warps, warp = 64oc x 64px)
// oc fastest -> CTAs sharing a pixel tile are schedule-adjacent (L1/L2 reuse)
template <bool HAS_BN>
__global__ __launch_bounds__(128, 2)
void conv3x3_mma(const float* __restrict__ X, const __half* __restrict__ wtp,
                 float* __restrict__ Y, int Cout,
                 const float* __restrict__ bnsc, const float* __restrict__ bnbi)
{
    extern __shared__ char sm[];
    const uint32_t smb = smem_u32(sm);

    const int tid  = threadIdx.x;
    const int wid  = tid >> 5;          // 0..3
    const int lane = tid & 31;
    const int r    = lane >> 2;
    const int q    = lane & 3;

    const int p0   = blockIdx.y * 128;
    const int oc0  = blockIdx.x * 128;
    const int bimg = p0 / HW;
    const int hw0  = p0 - bimg * HW;
    const float*  Xb  = X + (size_t)bimg * 256 * HW;
    const __half* wcb = wtp + (size_t)blockIdx.x * (NCHK * 8192);

    const int ocb = (wid & 1) * 64;     // warp oc sub-block (4 x m16)
    const int pxb = (wid >> 1) * 64;    // warp px sub-block (8 x n8)
    const int cw  = 2 * wid;            // B staging channel base within k16

    int pg[4], hh[4], ww[4];
    #pragma unroll
    for (int g = 0; g < 4; g++) {
        int p = hw0 + g * 32 + lane;
        pg[g] = p; hh[g] = p / W_; ww[g] = p % W_;
    }

    float acc[4][8][4];
    #pragma unroll
    for (int mt = 0; mt < 4; mt++)
        #pragma unroll
        for (int nt = 0; nt < 8; nt++)
            #pragma unroll
            for (int i = 0; i < 4; i++) acc[mt][nt][i] = 0.f;

    uint2 rb[4][4];    // [ks][px group]

    auto copyA = [&](int c, int s) {
        const char* g = (const char*)wcb + (size_t)c * A_BYTES + tid * 16;
        uint32_t d = smb + s * STG_BYTES + tid * 16;
        #pragma unroll
        for (int i = 0; i < 8; i++)
            cp_async16(d + i * 2048, g + i * 2048);
    };

    auto stageB = [&](int c) {
        const int tap = c >> 2;
        const int ci0 = (c & 3) << 6;
        const int dh  = tap / 3 - 1;
        const int dw  = tap % 3 - 1;
        #pragma unroll
        for (int ks = 0; ks < 4; ks++) {
            const int ch = ci0 + 16 * ks + cw;
            float sc0, sc1, sc2, sc3, bi0, bi1, bi2, bi3;
            if (HAS_BN) {
                sc0 = bnsc[ch];     bi0 = bnbi[ch];
                sc1 = bnsc[ch + 1]; bi1 = bnbi[ch + 1];
                sc2 = bnsc[ch + 8]; bi2 = bnbi[ch + 8];
                sc3 = bnsc[ch + 9]; bi3 = bnbi[ch + 9];
            }
            const float* base = Xb + (size_t)ch * HW + dh * W_ + dw;
            #pragma unroll
            for (int g = 0; g < 4; g++) {
                bool v = (unsigned)(hh[g] + dh) < (unsigned)H_ &&
                         (unsigned)(ww[g] + dw) < (unsigned)W_;
                const float* sp = base + pg[g];
                float x0 = v ? sp[0]              : 0.f;
                float x1 = v ? sp[(size_t)HW]     : 0.f;
                float x2 = v ? sp[(size_t)8 * HW] : 0.f;
                float x3 = v ? sp[(size_t)9 * HW] : 0.f;
                if (HAS_BN) {
                    x0 = v ? fmaxf(fmaf(x0, sc0, bi0), 0.f) : 0.f;
                    x1 = v ? fmaxf(fmaf(x1, sc1, bi1), 0.f) : 0.f;
                    x2 = v ? fmaxf(fmaf(x2, sc2, bi2), 0.f) : 0.f;
                    x3 = v ? fmaxf(fmaf(x3, sc3, bi3), 0.f) : 0.f;
                }
                rb[ks][g] = make_uint2(pack2h(x0, x1), pack2h(x2, x3));
            }
        }
    };

    auto stsB = [&](int s) {
        uint2* sB2 = (uint2*)(sm + s * STG_BYTES + A_BYTES);
        #pragma unroll
        for (int ks = 0; ks < 4; ks++)
            #pragma unroll
            for (int g = 0; g < 4; g++)
                sB2[(ks * 4 + wid) * BROW_U2 + g * 32 + lane] = rb[ks][g];
    };

    auto compute = [&](int s) {
        const char*  sbase = sm + s * STG_BYTES;
        const uint2* sB2   = (const uint2*)(sbase + A_BYTES);
        #pragma unroll
        for (int ks = 0; ks < 4; ks++) {
            const uint4* aP = (const uint4*)sbase + (ks * 8 + (wid & 1) * 4) * 32 + lane;
            uint32_t a[4][4];
            #pragma unroll
            for (int mt = 0; mt < 4; mt++) {
                uint4 A = aP[mt * 32];
                a[mt][0] = A.x; a[mt][1] = A.y; a[mt][2] = A.z; a[mt][3] = A.w;
            }
            const uint2* bP = sB2 + (ks * 4 + q) * BROW_U2 + pxb + r;
            #pragma unroll
            for (int nt = 0; nt < 8; nt++) {
                uint2 b = bP[nt * 8];
                #pragma unroll
                for (int mt = 0; mt < 4; mt++)
                    mma16(acc[mt][nt], a[mt], b.x, b.y);
            }
        }
    };

    // prologue
    copyA(0, 0); CP_COMMIT();
    stageB(0); stsB(0);
    CP_WAIT0();
    __syncthreads();

    for (int c = 0; c < NCHK; c++) {
        const int cur = c & 1, nxt = cur ^ 1;
        if (c + 1 < NCHK) {
            copyA(c + 1, nxt); CP_COMMIT();
            stageB(c + 1);
        }
        compute(cur);
        if (c + 1 < NCHK) {
            stsB(nxt);
            CP_WAIT0();
            __syncthreads();
        }
    }

    #pragma unroll
    for (int mt = 0; mt < 4; mt++) {
        const int oc = oc0 + ocb + mt * 16 + r;
        float* Yr = Y + ((size_t)bimg * Cout + oc) * HW + hw0 + pxb + q * 2;
        #pragma unroll
        for (int nt = 0; nt < 8; nt++) {
            *(float2*)(Yr + nt * 8)                  = make_float2(acc[mt][nt][0], acc[mt][nt][1]);
            *(float2*)(Yr + nt * 8 + 8 * (size_t)HW) = make_float2(acc[mt][nt][2], acc[mt][nt][3]);
        }
    }
}

// ---------------- per-channel batch stats -> fused scale/bias ---------------
__global__ __launch_bounds__(1024)
void bn_stats(const float* __restrict__ X, int C,
              const float* __restrict__ gamma, const float* __restrict__ beta,
              float* __restrict__ osc, float* __restrict__ obi)
{
    const int c = blockIdx.x;
    float s = 0.f, s2 = 0.f;
    for (int b = 0; b < B_; b++) {
        const float* qp = X + ((size_t)b * C + c) * HW;
        for (int i = threadIdx.x; i < HW; i += 1024) {
            float v = qp[i];
            s += v; s2 += v * v;
        }
    }
    __shared__ float rs[1024], rs2[1024];
    rs[threadIdx.x] = s; rs2[threadIdx.x] = s2;
    __syncthreads();
    for (int o = 512; o > 0; o >>= 1) {
        if (threadIdx.x < o) {
            rs[threadIdx.x]  += rs[threadIdx.x + o];
            rs2[threadIdx.x] += rs2[threadIdx.x + o];
        }
        __syncthreads();
    }
    if (threadIdx.x == 0) {
        const float cnt = (float)(B_ * HW);
        float m   = rs[0] / cnt;
        float var = rs2[0] / cnt - m * m;
        float is  = rsqrtf(var + 1e-5f);
        float scl = gamma[c] * is;
        osc[c] = scl;
        obi[c] = beta[c] - m * scl;
    }
}

// ---------------- head conv: 3x3 + bias, BN+ReLU fused on input -------------
#define HTH 16
#define HTW 32

template <int CO>
__global__ __launch_bounds__(256)
void head_conv(const float* __restrict__ X, const float* __restrict__ Wt,
               const float* __restrict__ bias, float* __restrict__ Y, int Cin,
               const float* __restrict__ bnsc, const float* __restrict__ bnbi,
               size_t strideC, size_t strideB)
{
    const int tile = blockIdx.x;
    const int tw0  = (tile % (W_ / HTW)) * HTW;
    const int th0  = (tile / (W_ / HTW)) * HTH;
    const int b    = blockIdx.z;
    const int t    = threadIdx.x;
    const int col  = t & 31;
    const int rp   = (t >> 5) * 2;

    __shared__ float sX[8][HTH + 2][HTW + 4];
    __shared__ float sW[8][9][CO];

    float acc[2][CO];
    #pragma unroll
    for (int r = 0; r < 2; r++)
        #pragma unroll
        for (int o = 0; o < CO; o++) acc[r][o] = 0.f;

    const float* Xb = X + (size_t)b * Cin * HW;

    for (int ci0 = 0; ci0 < Cin; ci0 += 8) {
        __syncthreads();
        for (int e = t; e < 8 * (HTH + 2) * 34; e += 256) {
            int ci  = e / ((HTH + 2) * 34);
            int rem = e % ((HTH + 2) * 34);
            int r   = rem / 34;
            int c   = rem % 34;
            int gh  = th0 + r - 1;
            int gw  = tw0 + c - 1;
            float v = 0.f;
            if (gh >= 0 && gh < H_ && gw >= 0 && gw < W_) {
                float x = Xb[(size_t)(ci0 + ci) * HW + gh * W_ + gw];
                v = fmaxf(fmaf(x, bnsc[ci0 + ci], bnbi[ci0 + ci]), 0.f);
            }
            sX[ci][r][c] = v;
        }
        for (int e = t; e < 8 * 9 * CO; e += 256) {
            int ci  = e / (9 * CO);
            int rem = e % (9 * CO);
            int tap = rem / CO;
            int oc  = rem % CO;
            sW[ci][tap][oc] = Wt[((size_t)oc * Cin + ci0 + ci) * 9 + tap];
        }
        __syncthreads();

        #pragma unroll 1
        for (int ci = 0; ci < 8; ci++) {
            float xv[4][3];
            #pragma unroll
            for (int rr = 0; rr < 4; rr++)
                #pragma unroll
                for (int cc = 0; cc < 3; cc++)
                    xv[rr][cc] = sX[ci][rp + rr][col + cc];
            #pragma unroll
            for (int oc = 0; oc < CO; oc++) {
                float w[9];
                #pragma unroll
                for (int tp = 0; tp < 9; tp++) w[tp] = sW[ci][tp][oc];
                #pragma unroll
                for (int orow = 0; orow < 2; orow++) {
                    float s = acc[orow][oc];
                    #pragma unroll
                    for (int kh = 0; kh < 3; kh++)
                        #pragma unroll
                        for (int kw = 0; kw < 3; kw++)
                            s += w[kh * 3 + kw] * xv[orow + kh][kw];
                    acc[orow][oc] = s;
                }
            }
        }
    }

    #pragma unroll
    for (int oc = 0; oc < CO; oc++) {
        const float bz = bias[oc];
        #pragma unroll
        for (int orow = 0; orow < 2; orow++) {
            const int h = th0 + rp + orow;
            Y[oc * strideC + b * strideB + h * W_ + tw0 + col] = acc[orow][oc] + bz;
        }
    }
}

// ---------------- launcher ---------------------------------------------------
struct BranchPtrs {
    const float *w1, *g1, *b1, *w2, *g2, *b2;
};

static void run_branch(cudaStream_t st, const float* fpn, const BranchPtrs& P,
                       float* buf1, float* buf2, __half* wt1, __half* wt2,
                       float* sc1, float* bi1, float* sc2, float* bi2)
{
    wt_pack<<<(256 * K2 + 255) / 256, 256, 0, st>>>(P.w1, wt1, 256);
    wt_pack<<<(128 * K2 + 255) / 256, 256, 0, st>>>(P.w2, wt2, 128);
    conv3x3_mma<false><<<dim3(2, NBX), 128, SMEM_DYN, st>>>(
        fpn, wt1, buf1, 256, nullptr, nullptr);
    bn_stats<<<256, 1024, 0, st>>>(buf1, 256, P.g1, P.b1, sc1, bi1);
    conv3x3_mma<true><<<dim3(1, NBX), 128, SMEM_DYN, st>>>(
        buf1, wt2, buf2, 128, sc1, bi1);
    bn_stats<<<128, 1024, 0, st>>>(buf2, 128, P.g2, P.b2, sc2, bi2);
}

extern "C" void kernel_launch(void* const* d_in, const int* in_sizes, int n_in,
                              void* d_out, int out_size)
{
    const float* fpn        = (const float*)d_in[0];
    BranchPtrs sc = { (const float*)d_in[1],  (const float*)d_in[2],  (const float*)d_in[3],
                      (const float*)d_in[4],  (const float*)d_in[5],  (const float*)d_in[6] };
    const float* w_shrink   = (const float*)d_in[7];
    const float* bias_shrink= (const float*)d_in[8];
    const float* w_cent     = (const float*)d_in[9];
    const float* bias_cent  = (const float*)d_in[10];
    BranchPtrs pp = { (const float*)d_in[11], (const float*)d_in[12], (const float*)d_in[13],
                      (const float*)d_in[14], (const float*)d_in[15], (const float*)d_in[16] };
    const float* w_p3       = (const float*)d_in[17];
    const float* bias_p3    = (const float*)d_in[18];
    BranchPtrs sh = { (const float*)d_in[19], (const float*)d_in[20], (const float*)d_in[21],
                      (const float*)d_in[22], (const float*)d_in[23], (const float*)d_in[24] };
    const float* w_s3       = (const float*)d_in[25];
    const float* bias_s3    = (const float*)d_in[26];

    float* out = (float*)d_out;

    static cudaStream_t s_st[3];
    static cudaEvent_t  s_fork, s_join[3];
    static int s_init = 0;
    if (!s_init) {
        for (int i = 0; i < 3; i++) {
            cudaStreamCreateWithFlags(&s_st[i], cudaStreamNonBlocking);
            cudaEventCreateWithFlags(&s_join[i], cudaEventDisableTiming);
        }
        cudaEventCreateWithFlags(&s_fork, cudaEventDisableTiming);
        s_init = 1;
    }

    float *buf1[3], *buf2[3];
    __half *wt1[3], *wt2[3];
    float *sc1[3], *bi1[3], *sc2[3], *bi2[3];
    float *wcat, *bcat;
    {
        float *p; __half *hp;
        cudaGetSymbolAddress((void**)&p, g_buf1);
        for (int i = 0; i < 3; i++) buf1[i] = p + (size_t)i * B_ * 256 * HW;
        cudaGetSymbolAddress((void**)&p, g_buf2);
        for (int i = 0; i < 3; i++) buf2[i] = p + (size_t)i * B_ * 128 * HW;
        cudaGetSymbolAddress((void**)&hp, g_wt1);
        for (int i = 0; i < 3; i++) wt1[i] = hp + (size_t)i * 2 * 36 * 8192;
        cudaGetSymbolAddress((void**)&hp, g_wt2);
        for (int i = 0; i < 3; i++) wt2[i] = hp + (size_t)i * 36 * 8192;
        cudaGetSymbolAddress((void**)&p, g_sc1);
        for (int i = 0; i < 3; i++) sc1[i] = p + i * 256;
        cudaGetSymbolAddress((void**)&p, g_bi1);
        for (int i = 0; i < 3; i++) bi1[i] = p + i * 256;
        cudaGetSymbolAddress((void**)&p, g_sc2);
        for (int i = 0; i < 3; i++) sc2[i] = p + i * 128;
        cudaGetSymbolAddress((void**)&p, g_bi2);
        for (int i = 0; i < 3; i++) bi2[i] = p + i * 128;
        cudaGetSymbolAddress((void**)&wcat, g_wcat);
        cudaGetSymbolAddress((void**)&bcat, g_bcat);
    }

    cudaFuncSetAttribute(conv3x3_mma<false>, cudaFuncAttributeMaxDynamicSharedMemorySize, SMEM_DYN);
    cudaFuncSetAttribute(conv3x3_mma<true>,  cudaFuncAttributeMaxDynamicSharedMemorySize, SMEM_DYN);

    dim3 hgrid(50, 1, B_);
    const size_t seg = (size_t)B_ * HW;

    // fork
    cudaEventRecord(s_fork, 0);
    for (int i = 0; i < 3; i++) cudaStreamWaitEvent(s_st[i], s_fork, 0);

    // branch 0: sc -> shrink + centroid (fused CO=2 head via weight concat)
    concat_heads<<<9, 256, 0, s_st[0]>>>(w_shrink, w_cent, bias_shrink, bias_cent,
                                         wcat, bcat);
    run_branch(s_st[0], fpn, sc, buf1[0], buf2[0], wt1[0], wt2[0],
               sc1[0], bi1[0], sc2[0], bi2[0]);
    head_conv<2><<<hgrid, 256, 0, s_st[0]>>>(buf2[0], wcat, bcat, out, 128,
                                             sc2[0], bi2[0], seg, (size_t)HW);

    // branch 1: param (B,2,H,W)
    run_branch(s_st[1], fpn, pp, buf1[1], buf2[1], wt1[1], wt2[1],
               sc1[1], bi1[1], sc2[1], bi2[1]);
    head_conv<2><<<hgrid, 256, 0, s_st[1]>>>(buf2[1], w_p3, bias_p3, out + 2 * seg, 128,
                                             sc2[1], bi2[1], (size_t)HW, (size_t)(2 * HW));

    // branch 2: shift (B,8,H,W)
    run_branch(s_st[2], fpn, sh, buf1[2], buf2[2], wt1[2], wt2[2],
               sc1[2], bi1[2], sc2[2], bi2[2]);
    head_conv<8><<<hgrid, 256, 0, s_st[2]>>>(buf2[2], w_s3, bias_s3, out + 4 * seg, 128,
                                             sc2[2], bi2[2], (size_t)HW, (size_t)(8 * HW));

    // join
    for (int i = 0; i < 3; i++) {
        cudaEventRecord(s_join[i], s_st[i]);
        cudaStreamWaitEvent(0, s_join[i], 0);
    }
}

// round 16
// speedup vs baseline: 1.1882x; 1.0160x over previous
#include <cuda_runtime.h>
#include <cuda_fp16.h>
#include <cstdint>
#include <cstddef>

#define H_   160
#define W_   160
#define B_   4
#define HW   (H_ * W_)
#define PIX  (B_ * HW)          // 102400
#define K2   2304               // 9 * 256
#define NCHK 36                 // K chunks of 64 (tap-major: tap*4 + cq)
#define NBX  (PIX / 128)        // 800

// ---------------- scratch (device globals; no allocation allowed) ----------
__device__ float  g_buf1[3][(size_t)B_ * 256 * HW];
__device__ float  g_buf2[3][(size_t)B_ * 128 * HW];
__device__ __half g_wt1[3][2 * 36 * 8192];        // packed fp16 conv1 weights
__device__ __half g_wt2[3][1 * 36 * 8192];        // packed fp16 conv2 weights
__device__ float  g_sc1[3 * 256], g_bi1[3 * 256];
__device__ float  g_sc2[3 * 128], g_bi2[3 * 128];
__device__ float  g_wcat[2 * 128 * 9];
__device__ float  g_bcat[2];

__device__ __forceinline__ uint32_t smem_u32(const void* p) {
    uint32_t a;
    asm("{ .reg .u64 t; cvta.to.shared.u64 t, %1; cvt.u32.u64 %0, t; }" : "=r"(a) : "l"(p));
    return a;
}
__device__ __forceinline__ void cp_async16(uint32_t saddr, const void* g) {
    asm volatile("cp.async.cg.shared.global [%0], [%1], 16;" :: "r"(saddr), "l"(g));
}
#define CP_COMMIT() asm volatile("cp.async.commit_group;" ::: "memory")
#define CP_WAIT0()  asm volatile("cp.async.wait_group 0;" ::: "memory")

__device__ __forceinline__ uint32_t pack2h(float x, float y) {
    __half2 h = __floats2half2_rn(x, y);
    return *(uint32_t*)&h;
}

// mma.sync m16n8k16 fp16 with fp32 accum (baseline PTX sm_80+)
__device__ __forceinline__ void mma16(float* d, const uint32_t* a, uint32_t b0, uint32_t b1) {
    asm volatile(
        "mma.sync.aligned.m16n8k16.row.col.f32.f16.f16.f32 "
        "{%0,%1,%2,%3}, {%4,%5,%6,%7}, {%8,%9}, {%0,%1,%2,%3};"
        : "+f"(d[0]), "+f"(d[1]), "+f"(d[2]), "+f"(d[3])
        : "r"(a[0]), "r"(a[1]), "r"(a[2]), "r"(a[3]), "r"(b0), "r"(b1));
}

// smem per stage: A fragment-packed 16384 B + B 16 rows x 132 uint2 (16896 B)
#define BROW_U2   132
#define A_BYTES   16384
#define B_BYTES   (16 * BROW_U2 * 8)     // 16896
#define STG_BYTES (A_BYTES + B_BYTES)    // 33280
#define SMEM_DYN  (2 * STG_BYTES)        // 66560

// ---------------- weight pack: [oc][ci][tap] -> m16n8k16 fragment order ----
__global__ void wt_pack(const float* __restrict__ w, __half* __restrict__ dst, int Cout)
{
    int i = blockIdx.x * 256 + threadIdx.x;
    if (i >= Cout * K2) return;
    int h     = i & 1;
    int jreg  = (i >> 1) & 3;
    int lane  = (i >> 3) & 31;
    int ocq   = (i >> 8) & 7;
    int ks    = (i >> 11) & 3;
    int chunk = (i >> 13) % NCHK;
    int ocblk = i / (NCHK * 8192);
    int q = lane & 3, r = lane >> 2;
    int row16 = r + 8 * (jreg & 1);
    int kk    = 2 * q + h + 8 * (jreg >> 1);
    int oc  = ocblk * 128 + ocq * 16 + row16;
    int ci  = (chunk & 3) * 64 + ks * 16 + kk;
    int tap = chunk >> 2;
    dst[i] = __float2half_rn(w[((size_t)oc * 256 + ci) * 9 + tap]);
}

// ---------------- concat two 1-channel head weights -------------------------
__global__ void concat_heads(const float* __restrict__ wa, const float* __restrict__ wb,
                             const float* __restrict__ ba, const float* __restrict__ bb,
                             float* __restrict__ w, float* __restrict__ bias)
{
    int i = blockIdx.x * 256 + threadIdx.x;
    if (i < 1152) w[i] = wa[i];
    else if (i < 2304) w[i] = wb[i - 1152];
    if (i == 0) { bias[0] = ba[0]; bias[1] = bb[0]; }
}

// ---------------- fp16 mma.sync implicit-GEMM 3x3 conv, branch-batched ------
// grid: (Cout/128, PIX/128, 3 branches)  block: 128 threads (4 warps, 64oc x 64px)
// oc fastest -> the 2*3 oc-blocks sharing a pixel tile are schedule-adjacent.
template <bool HAS_BN>
__global__ __launch_bounds__(128, 2)
void conv3x3_mma(const float* __restrict__ X, size_t xBrStride,
                 const __half* __restrict__ wtp,
                 float* __restrict__ Y, size_t yBrStride, int Cout,
                 const float* __restrict__ bnsc, const float* __restrict__ bnbi,
                 int bnBrStride)
{
    extern __shared__ char sm[];
    const uint32_t smb = smem_u32(sm);

    const int tid  = threadIdx.x;
    const int wid  = tid >> 5;          // 0..3
    const int lane = tid & 31;
    const int r    = lane >> 2;
    const int q    = lane & 3;
    const int bz   = blockIdx.z;

    const int p0   = blockIdx.y * 128;
    const int oc0  = blockIdx.x * 128;
    const int bimg = p0 / HW;
    const int hw0  = p0 - bimg * HW;
    const float*  Xb  = X + (size_t)bz * xBrStride + (size_t)bimg * 256 * HW;
    const __half* wcb = wtp + ((size_t)bz * gridDim.x + blockIdx.x) * (NCHK * 8192);
    float* Yb = Y + (size_t)bz * yBrStride;
    if (HAS_BN) {
        bnsc += bz * bnBrStride;
        bnbi += bz * bnBrStride;
    }

    const int ocb = (wid & 1) * 64;     // warp oc sub-block (4 x m16)
    const int pxb = (wid >> 1) * 64;    // warp px sub-block (8 x n8)
    const int cw  = 2 * wid;            // B staging channel base within k16

    int pg[4], hh[4], ww[4];
    #pragma unroll
    for (int g = 0; g < 4; g++) {
        int p = hw0 + g * 32 + lane;
        pg[g] = p; hh[g] = p / W_; ww[g] = p % W_;
    }

    float acc[4][8][4];
    #pragma unroll
    for (int mt = 0; mt < 4; mt++)
        #pragma unroll
        for (int nt = 0; nt < 8; nt++)
            #pragma unroll
            for (int i = 0; i < 4; i++) acc[mt][nt][i] = 0.f;

    uint2 rb[4][4];    // [ks][px group]

    auto copyA = [&](int c, int s) {
        const char* g = (const char*)wcb + (size_t)c * A_BYTES + tid * 16;
        uint32_t d = smb + s * STG_BYTES + tid * 16;
        #pragma unroll
        for (int i = 0; i < 8; i++)
            cp_async16(d + i * 2048, g + i * 2048);
    };

    auto stageB = [&](int c) {
        const int tap = c >> 2;
        const int ci0 = (c & 3) << 6;
        const int dh  = tap / 3 - 1;
        const int dw  = tap % 3 - 1;
        #pragma unroll
        for (int ks = 0; ks < 4; ks++) {
            const int ch = ci0 + 16 * ks + cw;
            float sc0, sc1, sc2, sc3, bi0, bi1, bi2, bi3;
            if (HAS_BN) {
                sc0 = bnsc[ch];     bi0 = bnbi[ch];
                sc1 = bnsc[ch + 1]; bi1 = bnbi[ch + 1];
                sc2 = bnsc[ch + 8]; bi2 = bnbi[ch + 8];
                sc3 = bnsc[ch + 9]; bi3 = bnbi[ch + 9];
            }
            const float* base = Xb + (size_t)ch * HW + dh * W_ + dw;
            #pragma unroll
            for (int g = 0; g < 4; g++) {
                bool v = (unsigned)(hh[g] + dh) < (unsigned)H_ &&
                         (unsigned)(ww[g] + dw) < (unsigned)W_;
                const float* sp = base + pg[g];
                float x0 = v ? sp[0]              : 0.f;
                float x1 = v ? sp[(size_t)HW]     : 0.f;
                float x2 = v ? sp[(size_t)8 * HW] : 0.f;
                float x3 = v ? sp[(size_t)9 * HW] : 0.f;
                if (HAS_BN) {
                    x0 = v ? fmaxf(fmaf(x0, sc0, bi0), 0.f) : 0.f;
                    x1 = v ? fmaxf(fmaf(x1, sc1, bi1), 0.f) : 0.f;
                    x2 = v ? fmaxf(fmaf(x2, sc2, bi2), 0.f) : 0.f;
                    x3 = v ? fmaxf(fmaf(x3, sc3, bi3), 0.f) : 0.f;
                }
                rb[ks][g] = make_uint2(pack2h(x0, x1), pack2h(x2, x3));
            }
        }
    };

    auto stsB = [&](int s) {
        uint2* sB2 = (uint2*)(sm + s * STG_BYTES + A_BYTES);
        #pragma unroll
        for (int ks = 0; ks < 4; ks++)
            #pragma unroll
            for (int g = 0; g < 4; g++)
                sB2[(ks * 4 + wid) * BROW_U2 + g * 32 + lane] = rb[ks][g];
    };

    auto compute = [&](int s) {
        const char*  sbase = sm + s * STG_BYTES;
        const uint2* sB2   = (const uint2*)(sbase + A_BYTES);
        #pragma unroll
        for (int ks = 0; ks < 4; ks++) {
            const uint4* aP = (const uint4*)sbase + (ks * 8 + (wid & 1) * 4) * 32 + lane;
            uint32_t a[4][4];
            #pragma unroll
            for (int mt = 0; mt < 4; mt++) {
                uint4 A = aP[mt * 32];
                a[mt][0] = A.x; a[mt][1] = A.y; a[mt][2] = A.z; a[mt][3] = A.w;
            }
            const uint2* bP = sB2 + (ks * 4 + q) * BROW_U2 + pxb + r;
            #pragma unroll
            for (int nt = 0; nt < 8; nt++) {
                uint2 b = bP[nt * 8];
                #pragma unroll
                for (int mt = 0; mt < 4; mt++)
                    mma16(acc[mt][nt], a[mt], b.x, b.y);
            }
        }
    };

    // prologue
    copyA(0, 0); CP_COMMIT();
    stageB(0); stsB(0);
    CP_WAIT0();
    __syncthreads();

    for (int c = 0; c < NCHK; c++) {
        const int cur = c & 1, nxt = cur ^ 1;
        if (c + 1 < NCHK) {
            copyA(c + 1, nxt); CP_COMMIT();
            stageB(c + 1);
        }
        compute(cur);
        if (c + 1 < NCHK) {
            stsB(nxt);
            CP_WAIT0();
            __syncthreads();
        }
    }

    #pragma unroll
    for (int mt = 0; mt < 4; mt++) {
        const int oc = oc0 + ocb + mt * 16 + r;
        float* Yr = Yb + ((size_t)bimg * Cout + oc) * HW + hw0 + pxb + q * 2;
        #pragma unroll
        for (int nt = 0; nt < 8; nt++) {
            *(float2*)(Yr + nt * 8)                  = make_float2(acc[mt][nt][0], acc[mt][nt][1]);
            *(float2*)(Yr + nt * 8 + 8 * (size_t)HW) = make_float2(acc[mt][nt][2], acc[mt][nt][3]);
        }
    }
}

// ---------------- per-channel batch stats -> fused scale/bias (3 branches) --
__global__ __launch_bounds__(1024)
void bn_stats(const float* __restrict__ X, int C,
              const float* __restrict__ g0, const float* __restrict__ g1,
              const float* __restrict__ g2,
              const float* __restrict__ b0, const float* __restrict__ b1,
              const float* __restrict__ b2,
              float* __restrict__ osc, float* __restrict__ obi)
{
    const int c  = blockIdx.x;
    const int bz = blockIdx.y;
    const float* gamma = bz == 0 ? g0 : (bz == 1 ? g1 : g2);
    const float* beta  = bz == 0 ? b0 : (bz == 1 ? b1 : b2);
    const float* Xb = X + (size_t)bz * B_ * C * HW;

    float s = 0.f, s2 = 0.f;
    for (int b = 0; b < B_; b++) {
        const float* qp = Xb + ((size_t)b * C + c) * HW;
        for (int i = threadIdx.x; i < HW; i += 1024) {
            float v = qp[i];
            s += v; s2 += v * v;
        }
    }
    __shared__ float rs[1024], rs2[1024];
    rs[threadIdx.x] = s; rs2[threadIdx.x] = s2;
    __syncthreads();
    for (int o = 512; o > 0; o >>= 1) {
        if (threadIdx.x < o) {
            rs[threadIdx.x]  += rs[threadIdx.x + o];
            rs2[threadIdx.x] += rs2[threadIdx.x + o];
        }
        __syncthreads();
    }
    if (threadIdx.x == 0) {
        const float cnt = (float)(B_ * HW);
        float m   = rs[0] / cnt;
        float var = rs2[0] / cnt - m * m;
        float is  = rsqrtf(var + 1e-5f);
        float scl = gamma[c] * is;
        osc[bz * C + c] = scl;
        obi[bz * C + c] = beta[c] - m * scl;
    }
}

// ---------------- head conv: 3x3 + bias, BN+ReLU fused on input -------------
#define HTH 16
#define HTW 32

template <int CO>
__global__ __launch_bounds__(256)
void head_conv(const float* __restrict__ X, const float* __restrict__ Wt,
               const float* __restrict__ bias, float* __restrict__ Y, int Cin,
               const float* __restrict__ bnsc, const float* __restrict__ bnbi,
               size_t strideC, size_t strideB)
{
    const int tile = blockIdx.x;
    const int tw0  = (tile % (W_ / HTW)) * HTW;
    const int th0  = (tile / (W_ / HTW)) * HTH;
    const int b    = blockIdx.z;
    const int t    = threadIdx.x;
    const int col  = t & 31;
    const int rp   = (t >> 5) * 2;

    __shared__ float sX[8][HTH + 2][HTW + 4];
    __shared__ float sW[8][9][CO];

    float acc[2][CO];
    #pragma unroll
    for (int r = 0; r < 2; r++)
        #pragma unroll
        for (int o = 0; o < CO; o++) acc[r][o] = 0.f;

    const float* Xb = X + (size_t)b * Cin * HW;

    for (int ci0 = 0; ci0 < Cin; ci0 += 8) {
        __syncthreads();
        for (int e = t; e < 8 * (HTH + 2) * 34; e += 256) {
            int ci  = e / ((HTH + 2) * 34);
            int rem = e % ((HTH + 2) * 34);
            int r   = rem / 34;
            int c   = rem % 34;
            int gh  = th0 + r - 1;
            int gw  = tw0 + c - 1;
            float v = 0.f;
            if (gh >= 0 && gh < H_ && gw >= 0 && gw < W_) {
                float x = Xb[(size_t)(ci0 + ci) * HW + gh * W_ + gw];
                v = fmaxf(fmaf(x, bnsc[ci0 + ci], bnbi[ci0 + ci]), 0.f);
            }
            sX[ci][r][c] = v;
        }
        for (int e = t; e < 8 * 9 * CO; e += 256) {
            int ci  = e / (9 * CO);
            int rem = e % (9 * CO);
            int tap = rem / CO;
            int oc  = rem % CO;
            sW[ci][tap][oc] = Wt[((size_t)oc * Cin + ci0 + ci) * 9 + tap];
        }
        __syncthreads();

        #pragma unroll 1
        for (int ci = 0; ci < 8; ci++) {
            float xv[4][3];
            #pragma unroll
            for (int rr = 0; rr < 4; rr++)
                #pragma unroll
                for (int cc = 0; cc < 3; cc++)
                    xv[rr][cc] = sX[ci][rp + rr][col + cc];
            #pragma unroll
            for (int oc = 0; oc < CO; oc++) {
                float w[9];
                #pragma unroll
                for (int tp = 0; tp < 9; tp++) w[tp] = sW[ci][tp][oc];
                #pragma unroll
                for (int orow = 0; orow < 2; orow++) {
                    float s = acc[orow][oc];
                    #pragma unroll
                    for (int kh = 0; kh < 3; kh++)
                        #pragma unroll
                        for (int kw = 0; kw < 3; kw++)
                            s += w[kh * 3 + kw] * xv[orow + kh][kw];
                    acc[orow][oc] = s;
                }
            }
        }
    }

    #pragma unroll
    for (int oc = 0; oc < CO; oc++) {
        const float bz = bias[oc];
        #pragma unroll
        for (int orow = 0; orow < 2; orow++) {
            const int h = th0 + rp + orow;
            Y[oc * strideC + b * strideB + h * W_ + tw0 + col] = acc[orow][oc] + bz;
        }
    }
}

// ---------------- launcher ---------------------------------------------------
extern "C" void kernel_launch(void* const* d_in, const int* in_sizes, int n_in,
                              void* d_out, int out_size)
{
    const float* fpn        = (const float*)d_in[0];
    const float* w_sc1      = (const float*)d_in[1];
    const float* g_sc1p     = (const float*)d_in[2];
    const float* b_sc1p     = (const float*)d_in[3];
    const float* w_sc2      = (const float*)d_in[4];
    const float* g_sc2p     = (const float*)d_in[5];
    const float* b_sc2p     = (const float*)d_in[6];
    const float* w_shrink   = (const float*)d_in[7];
    const float* bias_shrink= (const float*)d_in[8];
    const float* w_cent     = (const float*)d_in[9];
    const float* bias_cent  = (const float*)d_in[10];
    const float* w_p1       = (const float*)d_in[11];
    const float* g_p1       = (const float*)d_in[12];
    const float* b_p1       = (const float*)d_in[13];
    const float* w_p2       = (const float*)d_in[14];
    const float* g_p2       = (const float*)d_in[15];
    const float* b_p2       = (const float*)d_in[16];
    const float* w_p3       = (const float*)d_in[17];
    const float* bias_p3    = (const float*)d_in[18];
    const float* w_s1       = (const float*)d_in[19];
    const float* g_s1       = (const float*)d_in[20];
    const float* b_s1       = (const float*)d_in[21];
    const float* w_s2       = (const float*)d_in[22];
    const float* g_s2       = (const float*)d_in[23];
    const float* b_s2       = (const float*)d_in[24];
    const float* w_s3       = (const float*)d_in[25];
    const float* bias_s3    = (const float*)d_in[26];

    float* out = (float*)d_out;

    static cudaStream_t s_st[3];
    static cudaEvent_t  s_fork, s_join[3];
    static int s_init = 0;
    if (!s_init) {
        for (int i = 0; i < 3; i++) {
            cudaStreamCreateWithFlags(&s_st[i], cudaStreamNonBlocking);
            cudaEventCreateWithFlags(&s_join[i], cudaEventDisableTiming);
        }
        cudaEventCreateWithFlags(&s_fork, cudaEventDisableTiming);
        s_init = 1;
    }

    float *buf1, *buf2, *sc1, *bi1, *sc2, *bi2, *wcat, *bcat;
    __half *wt1, *wt2;
    cudaGetSymbolAddress((void**)&buf1, g_buf1);
    cudaGetSymbolAddress((void**)&buf2, g_buf2);
    cudaGetSymbolAddress((void**)&wt1,  g_wt1);
    cudaGetSymbolAddress((void**)&wt2,  g_wt2);
    cudaGetSymbolAddress((void**)&sc1,  g_sc1);
    cudaGetSymbolAddress((void**)&bi1,  g_bi1);
    cudaGetSymbolAddress((void**)&sc2,  g_sc2);
    cudaGetSymbolAddress((void**)&bi2,  g_bi2);
    cudaGetSymbolAddress((void**)&wcat, g_wcat);
    cudaGetSymbolAddress((void**)&bcat, g_bcat);

    cudaFuncSetAttribute(conv3x3_mma<false>, cudaFuncAttributeMaxDynamicSharedMemorySize, SMEM_DYN);
    cudaFuncSetAttribute(conv3x3_mma<true>,  cudaFuncAttributeMaxDynamicSharedMemorySize, SMEM_DYN);

    const size_t br1 = (size_t)B_ * 256 * HW;   // buf1 branch stride
    const size_t br2 = (size_t)B_ * 128 * HW;   // buf2 branch stride
    const size_t wbr1 = 2 * 36 * 8192;
    const size_t wbr2 = 36 * 8192;
    const size_t seg = (size_t)B_ * HW;

    // ---- weight packs + head concat (small, serial on stream 0) ----
    concat_heads<<<9, 256>>>(w_shrink, w_cent, bias_shrink, bias_cent, wcat, bcat);
    wt_pack<<<(256 * K2 + 255) / 256, 256>>>(w_sc1, wt1,            256);
    wt_pack<<<(256 * K2 + 255) / 256, 256>>>(w_p1,  wt1 + wbr1,     256);
    wt_pack<<<(256 * K2 + 255) / 256, 256>>>(w_s1,  wt1 + 2 * wbr1, 256);
    wt_pack<<<(128 * K2 + 255) / 256, 256>>>(w_sc2, wt2,            128);
    wt_pack<<<(128 * K2 + 255) / 256, 256>>>(w_p2,  wt2 + wbr2,     128);
    wt_pack<<<(128 * K2 + 255) / 256, 256>>>(w_s2,  wt2 + 2 * wbr2, 128);

    // ---- branch-batched main chain (stream 0) ----
    conv3x3_mma<false><<<dim3(2, NBX, 3), 128, SMEM_DYN>>>(
        fpn, 0, wt1, buf1, br1, 256, nullptr, nullptr, 0);
    bn_stats<<<dim3(256, 3), 1024>>>(buf1, 256,
        g_sc1p, g_p1, g_s1, b_sc1p, b_p1, b_s1, sc1, bi1);
    conv3x3_mma<true><<<dim3(1, NBX, 3), 128, SMEM_DYN>>>(
        buf1, br1, wt2, buf2, br2, 128, sc1, bi1, 256);
    bn_stats<<<dim3(128, 3), 1024>>>(buf2, 128,
        g_sc2p, g_p2, g_s2, b_sc2p, b_p2, b_s2, sc2, bi2);

    // ---- heads in parallel streams ----
    cudaEventRecord(s_fork, 0);
    for (int i = 0; i < 3; i++) cudaStreamWaitEvent(s_st[i], s_fork, 0);

    dim3 hgrid(50, 1, B_);
    head_conv<2><<<hgrid, 256, 0, s_st[0]>>>(buf2, wcat, bcat, out, 128,
                                             sc2, bi2, seg, (size_t)HW);
    head_conv<2><<<hgrid, 256, 0, s_st[1]>>>(buf2 + br2, w_p3, bias_p3, out + 2 * seg, 128,
                                             sc2 + 128, bi2 + 128, (size_t)HW, (size_t)(2 * HW));
    head_conv<8><<<hgrid, 256, 0, s_st[2]>>>(buf2 + 2 * br2, w_s3, bias_s3, out + 4 * seg, 128,
                                             sc2 + 256, bi2 + 256, (size_t)HW, (size_t)(8 * HW));

    for (int i = 0; i < 3; i++) {
        cudaEventRecord(s_join[i], s_st[i]);
        cudaStreamWaitEvent(0, s_join[i], 0);
    }
}